// round 2
// baseline (speedup 1.0000x reference)
#include <cuda_runtime.h>
#include <cstdint>

#define BB 4
#define SQ 4
#define HH 32
#define HKV 8
#define GG 4
#define DD 128
#define DVV 128
#define SMAX 8192
#define RR 16
#define TT 64
#define NSPLIT 16
#define CHUNK (SMAX / NSPLIT)
#define NTHREADS 256
#define SCALE 0.08838834764831845f

// smem layout (bytes):
//  qs4 : 16*32 float4              = 8192
//  ks4 : 2 * 64*32 float4          = 65536
//  vs4 : 2 * 64*32 float4          = 65536
//  sS  : 64*17 float               = 4352
//  sM/sL/sC : 3*16 float           = 192
#define SMEM_Q_OFF 0
#define SMEM_K_OFF 8192
#define SMEM_V_OFF (8192 + 65536)
#define SMEM_S_OFF (8192 + 65536 + 65536)
#define SMEM_M_OFF (SMEM_S_OFF + 4352)
#define SMEM_BYTES (SMEM_M_OFF + 192)

// split-K partial scratch (static device memory; no allocation)
__device__ float g_po[(size_t)BB * HKV * NSPLIT * RR * DVV];
__device__ float g_pm[BB * HKV * NSPLIT * RR];
__device__ float g_pl[BB * HKV * NSPLIT * RR];

extern "C" __global__ void __launch_bounds__(NTHREADS, 1)
attn_split_kernel(const float* __restrict__ Q, const float* __restrict__ K,
                  const float* __restrict__ V, const int* __restrict__ seqlens)
{
    extern __shared__ char smem[];
    float4* qs4 = (float4*)(smem + SMEM_Q_OFF);
    float4* ks4 = (float4*)(smem + SMEM_K_OFF);
    float4* vs4 = (float4*)(smem + SMEM_V_OFF);
    float*  sS  = (float*)(smem + SMEM_S_OFF);
    float*  sM  = (float*)(smem + SMEM_M_OFF);
    float*  sL  = sM + 16;
    float*  sC  = sM + 32;

    const int split = blockIdx.x;
    const int hkv   = blockIdx.y;
    const int b     = blockIdx.z;
    const int tid   = threadIdx.x;
    const int lane  = tid & 31;
    const int wid   = tid >> 5;

    const int L     = seqlens[b];
    const int c0    = split * CHUNK;
    int n_eff = L - c0;
    if (n_eff > CHUNK) n_eff = CHUNK;
    const int part  = (b * HKV + hkv) * NSPLIT + split;

    if (tid < RR) { sM[tid] = -1e30f; sL[tid] = 0.f; }

    // PV / output ownership: warp owns d-columns [16*wid, 16*wid+16)
    const int pr = lane >> 1;                      // row 0..15
    const int pd = (wid << 4) + ((lane & 1) << 3); // d base (8 floats)
    float o[8];
#pragma unroll
    for (int i = 0; i < 8; i++) o[i] = 0.f;

    if (n_eff > 0) {
        // ---- load Q (pre-scaled) into smem ----
#pragma unroll
        for (int i = 0; i < 2; i++) {
            int f  = tid * 2 + i;       // 0..511 float4 slots
            int r  = f >> 5;
            int d4 = f & 31;
            int h  = hkv * GG + (r >> 2);
            int m  = r & 3;
            const float4 qv = *(const float4*)(Q + ((size_t)((b * SQ + m) * HH + h)) * DD + d4 * 4);
            float4 qq;
            qq.x = qv.x * SCALE; qq.y = qv.y * SCALE;
            qq.z = qv.z * SCALE; qq.w = qv.w * SCALE;
            qs4[f] = qq;
        }
        __syncthreads();

        const int ntiles = (n_eff + TT - 1) / TT;
        const size_t kvbase = ((size_t)b * SMAX * HKV + hkv) * DD;

        auto issue_tile = [&](int it) {
            const int jb   = c0 + it * TT;
            const int bufo = (it & 1) * (TT * 32);
#pragma unroll
            for (int i = 0; i < 8; i++) {
                int f  = i * NTHREADS + tid;  // 0..2047
                int t  = f >> 5;
                int d4 = f & 31;
                const float* gk = K + kvbase + (size_t)(jb + t) * (HKV * DD) + d4 * 4;
                const float* gv = V + kvbase + (size_t)(jb + t) * (HKV * DD) + d4 * 4;
                unsigned ka = (unsigned)__cvta_generic_to_shared(&ks4[bufo + t * 32 + (d4 ^ ((t >> 1) & 31))]);
                unsigned va = (unsigned)__cvta_generic_to_shared(&vs4[bufo + t * 32 + d4]);
                asm volatile("cp.async.cg.shared.global [%0], [%1], 16;\n" :: "r"(ka), "l"(gk));
                asm volatile("cp.async.cg.shared.global [%0], [%1], 16;\n" :: "r"(va), "l"(gv));
            }
            asm volatile("cp.async.commit_group;\n" ::: "memory");
        };

        issue_tile(0);

        const int r2 = wid;          // row-pair id
        const int t0 = lane * 2;
        const int t1 = lane * 2 + 1;

        for (int it = 0; it < ntiles; ++it) {
            const bool more = (it + 1 < ntiles);
            if (more) issue_tile(it + 1);
            if (more) asm volatile("cp.async.wait_group 1;\n" ::: "memory");
            else      asm volatile("cp.async.wait_group 0;\n" ::: "memory");
            __syncthreads();

            const int bufo = (it & 1) * (TT * 32);
            const float4* kbuf = ks4 + bufo;

            // ---- S = Q K^T  (2 rows x 2 tokens per thread) ----
            float a00 = 0.f, a01 = 0.f, a10 = 0.f, a11 = 0.f;
#pragma unroll
            for (int d4 = 0; d4 < 32; ++d4) {
                float4 qa = qs4[(2 * r2) * 32 + d4];
                float4 qb = qs4[(2 * r2 + 1) * 32 + d4];
                int col = d4 ^ lane;
                float4 ka = kbuf[t0 * 32 + col];
                float4 kb = kbuf[t1 * 32 + col];
                a00 += qa.x * ka.x + qa.y * ka.y + qa.z * ka.z + qa.w * ka.w;
                a01 += qa.x * kb.x + qa.y * kb.y + qa.z * kb.z + qa.w * kb.w;
                a10 += qb.x * ka.x + qb.y * ka.y + qb.z * ka.z + qb.w * ka.w;
                a11 += qb.x * kb.x + qb.y * kb.y + qb.z * kb.z + qb.w * kb.w;
            }

            // ---- mask + stage scores ----
            {
                const int jb = c0 + it * TT;
                int r   = 2 * r2;
                int lim = L - SQ + (r & 3);
                sS[t0 * 17 + r] = (jb + t0 <= lim) ? a00 : -1e30f;
                sS[t1 * 17 + r] = (jb + t1 <= lim) ? a01 : -1e30f;
                r   = 2 * r2 + 1;
                lim = L - SQ + (r & 3);
                sS[t0 * 17 + r] = (jb + t0 <= lim) ? a10 : -1e30f;
                sS[t1 * 17 + r] = (jb + t1 <= lim) ? a11 : -1e30f;
            }
            __syncthreads();

            // ---- online softmax row pass (16 threads) ----
            if (tid < RR) {
                const int r = tid;
                float mx = -1e30f;
#pragma unroll 8
                for (int t = 0; t < TT; t++) mx = fmaxf(mx, sS[t * 17 + r]);
                float mOld = sM[r];
                float nm   = fmaxf(mOld, mx);
                float corr = __expf(mOld - nm);
                float sum  = 0.f;
#pragma unroll 8
                for (int t = 0; t < TT; t++) {
                    float p = __expf(sS[t * 17 + r] - nm);
                    sS[t * 17 + r] = p;
                    sum += p;
                }
                sL[r] = sL[r] * corr + sum;
                sM[r] = nm;
                sC[r] = corr;
            }
            __syncthreads();

            // ---- O += P V ----
            {
                float corr = sC[pr];
#pragma unroll
                for (int i = 0; i < 8; i++) o[i] *= corr;
                const float4* vbuf = vs4 + bufo;
                const int vd = pd >> 2;  // float4 column
#pragma unroll 4
                for (int t = 0; t < TT; t++) {
                    float p  = sS[t * 17 + pr];
                    float4 v0 = vbuf[t * 32 + vd];
                    float4 v1 = vbuf[t * 32 + vd + 1];
                    o[0] += p * v0.x; o[1] += p * v0.y;
                    o[2] += p * v0.z; o[3] += p * v0.w;
                    o[4] += p * v1.x; o[5] += p * v1.y;
                    o[6] += p * v1.z; o[7] += p * v1.w;
                }
            }
            __syncthreads();
        }
    }

    // ---- store split partials ----
    {
        float* po = g_po + ((size_t)part * RR) * DVV;
        *(float4*)(po + pr * DVV + pd)     = make_float4(o[0], o[1], o[2], o[3]);
        *(float4*)(po + pr * DVV + pd + 4) = make_float4(o[4], o[5], o[6], o[7]);
        if (tid < RR) {
            g_pm[part * RR + tid] = sM[tid];
            g_pl[part * RR + tid] = sL[tid];
        }
    }
}

extern "C" __global__ void __launch_bounds__(256)
attn_reduce_kernel(float* __restrict__ out)
{
    const int hkv = blockIdx.x;
    const int b   = blockIdx.y;
    const int tid = threadIdx.x;
    const int r   = tid >> 4;          // 0..15
    const int ds  = (tid & 15) * 8;    // 0..120
    const int pb  = (b * HKV + hkv) * NSPLIT;

    float M = -1e30f;
#pragma unroll
    for (int s = 0; s < NSPLIT; s++) M = fmaxf(M, g_pm[(pb + s) * RR + r]);

    float lt = 0.f;
    float o[8];
#pragma unroll
    for (int i = 0; i < 8; i++) o[i] = 0.f;

#pragma unroll
    for (int s = 0; s < NSPLIT; s++) {
        float mm = g_pm[(pb + s) * RR + r];
        float w  = __expf(mm - M);
        lt += w * g_pl[(pb + s) * RR + r];
        const float4* src = (const float4*)(g_po + ((size_t)(pb + s) * RR + r) * DVV + ds);
        float4 x = src[0];
        float4 y = src[1];
        o[0] += w * x.x; o[1] += w * x.y; o[2] += w * x.z; o[3] += w * x.w;
        o[4] += w * y.x; o[5] += w * y.y; o[6] += w * y.z; o[7] += w * y.w;
    }

    const float inv = 1.f / lt;
    const int m  = r & 3;
    const int gi = r >> 2;
    float* dst = out + ((size_t)((b * SQ + m) * HH + hkv * GG + gi)) * DVV + ds;
    ((float4*)dst)[0] = make_float4(o[0] * inv, o[1] * inv, o[2] * inv, o[3] * inv);
    ((float4*)dst)[1] = make_float4(o[4] * inv, o[5] * inv, o[6] * inv, o[7] * inv);
}

extern "C" void kernel_launch(void* const* d_in, const int* in_sizes, int n_in,
                              void* d_out, int out_size)
{
    const float* Q  = (const float*)d_in[0];
    const float* K  = (const float*)d_in[1];
    const float* V  = (const float*)d_in[2];
    const int*   sl = (const int*)d_in[3];

    cudaFuncSetAttribute(attn_split_kernel,
                         cudaFuncAttributeMaxDynamicSharedMemorySize, SMEM_BYTES);

    attn_split_kernel<<<dim3(NSPLIT, HKV, BB), NTHREADS, SMEM_BYTES>>>(Q, K, V, sl);
    attn_reduce_kernel<<<dim3(HKV, BB), 256>>>((float*)d_out);
}

// round 3
// speedup vs baseline: 1.3094x; 1.3094x over previous
#include <cuda_runtime.h>
#include <cstdint>

#define BB 4
#define SQ 4
#define HH 32
#define HKV 8
#define GG 4
#define DD 128
#define DVV 128
#define SMAX 8192
#define RR 16
#define TT 64
#define NSPLIT 16
#define CHUNK (SMAX / NSPLIT)
#define NTHREADS 256
#define SCALE 0.08838834764831845f

// smem layout (bytes)
#define SMEM_Q_OFF 0
#define SMEM_K_OFF 8192
#define SMEM_V_OFF (8192 + 65536)
#define SMEM_SRAW_OFF (8192 + 65536 + 65536)            // [2][64][17] float = 8704
#define SMEM_PD_OFF (SMEM_SRAW_OFF + 8704)              // [64][17] float2  = 8704
#define SMEM_M_OFF (SMEM_PD_OFF + 8704)                 // sM/sL/sC 3*16 float
#define SMEM_BYTES (SMEM_M_OFF + 192)

typedef unsigned long long u64;

__device__ __forceinline__ void fma2(u64& d, u64 a, u64 b) {
    asm("fma.rn.f32x2 %0, %1, %2, %0;" : "+l"(d) : "l"(a), "l"(b));
}
__device__ __forceinline__ void mul2(u64& d, u64 a) {
    asm("mul.rn.f32x2 %0, %0, %1;" : "+l"(d) : "l"(a));
}
__device__ __forceinline__ u64 pack2(float x) {
    u64 r; asm("mov.b64 %0, {%1, %1};" : "=l"(r) : "f"(x)); return r;
}
__device__ __forceinline__ float2 unpack2(u64 a) {
    float2 f; asm("mov.b64 {%0, %1}, %2;" : "=f"(f.x), "=f"(f.y) : "l"(a)); return f;
}

// split-K partial scratch (static device memory; no allocation)
__device__ float g_po[(size_t)BB * HKV * NSPLIT * RR * DVV];
__device__ float g_pm[BB * HKV * NSPLIT * RR];
__device__ float g_pl[BB * HKV * NSPLIT * RR];

extern "C" __global__ void __launch_bounds__(NTHREADS, 1)
attn_split_kernel(const float* __restrict__ Q, const float* __restrict__ K,
                  const float* __restrict__ V, const int* __restrict__ seqlens)
{
    extern __shared__ char smem[];
    float4* qs4  = (float4*)(smem + SMEM_Q_OFF);
    float4* ks4  = (float4*)(smem + SMEM_K_OFF);
    float4* vs4  = (float4*)(smem + SMEM_V_OFF);
    float*  sraw = (float*)(smem + SMEM_SRAW_OFF);     // [dh][t][17]
    float2* sPd  = (float2*)(smem + SMEM_PD_OFF);      // [t][17]
    float*  sM   = (float*)(smem + SMEM_M_OFF);
    float*  sL   = sM + 16;
    float*  sC   = sM + 32;

    const int split = blockIdx.x;
    const int hkv   = blockIdx.y;
    const int b     = blockIdx.z;
    const int tid   = threadIdx.x;
    const int lane  = tid & 31;
    const int wid   = tid >> 5;

    const int L  = seqlens[b];
    const int c0 = split * CHUNK;
    int n_eff = L - c0;
    if (n_eff > CHUNK) n_eff = CHUNK;
    const int part = (b * HKV + hkv) * NSPLIT + split;

    if (tid < RR) { sM[tid] = -1e30f; sL[tid] = 0.f; }

    // PV ownership: warp owns d-cols [16*wid,16*wid+16)
    const int pr = lane >> 1;                       // row 0..15
    const int pd = (wid << 4) + ((lane & 1) << 3);  // d base (8 floats)
    u64 o[4];
#pragma unroll
    for (int i = 0; i < 4; i++) o[i] = 0ull;

    if (n_eff > 0) {
        // ---- Q (pre-scaled) into smem ----
#pragma unroll
        for (int i = 0; i < 2; i++) {
            int f  = tid * 2 + i;
            int r  = f >> 5;
            int d4 = f & 31;
            int h  = hkv * GG + (r >> 2);
            int m  = r & 3;
            const float4 qv = *(const float4*)(Q + ((size_t)((b * SQ + m) * HH + h)) * DD + d4 * 4);
            float4 qq;
            qq.x = qv.x * SCALE; qq.y = qv.y * SCALE;
            qq.z = qv.z * SCALE; qq.w = qv.w * SCALE;
            qs4[f] = qq;
        }
        __syncthreads();

        const int ntiles = (n_eff + TT - 1) / TT;
        const size_t kvbase = ((size_t)b * SMAX * HKV + hkv) * DD;

        auto issue_tile = [&](int it) {
            const int jb   = c0 + it * TT;
            const int bufo = (it & 1) * (TT * 32);
#pragma unroll
            for (int i = 0; i < 8; i++) {
                int f  = i * NTHREADS + tid;
                int t  = f >> 5;
                int d4 = f & 31;
                const float* gk = K + kvbase + (size_t)(jb + t) * (HKV * DD) + d4 * 4;
                const float* gv = V + kvbase + (size_t)(jb + t) * (HKV * DD) + d4 * 4;
                unsigned ka = (unsigned)__cvta_generic_to_shared(&ks4[bufo + t * 32 + (d4 ^ ((t >> 1) & 31))]);
                unsigned va = (unsigned)__cvta_generic_to_shared(&vs4[bufo + t * 32 + d4]);
                asm volatile("cp.async.cg.shared.global [%0], [%1], 16;\n" :: "r"(ka), "l"(gk));
                asm volatile("cp.async.cg.shared.global [%0], [%1], 16;\n" :: "r"(va), "l"(gv));
            }
            asm volatile("cp.async.commit_group;\n" ::: "memory");
        };

        issue_tile(0);
        if (ntiles > 1) issue_tile(1);

        // QK mapping: warp wid -> rows 4*(wid&3)..+3, dim-half (wid>>2)
        const int R      = (wid & 3) * 4;
        const int d4base = (wid >> 2) * 16;
        const int t0     = 2 * lane;
        // softmax mapping
        const int sr  = tid >> 4;
        const int sub = tid & 15;
        const int tb  = sub * 4;
        const int lim = L - SQ + (sr & 3);

        for (int it = 0; it < ntiles; ++it) {
            if (it < ntiles - 1) asm volatile("cp.async.wait_group 1;\n" ::: "memory");
            else                 asm volatile("cp.async.wait_group 0;\n" ::: "memory");
            __syncthreads();

            const int jb   = c0 + it * TT;
            const int bufo = (it & 1) * (TT * 32);

            // ---- S = Q K^T : 4 rows x 2 tokens per thread, packed dim-pairs ----
            {
                const ulonglong2* kb = (const ulonglong2*)(ks4 + bufo);
                const ulonglong2* qb = (const ulonglong2*)qs4;
                u64 acc[4][2];
#pragma unroll
                for (int rr = 0; rr < 4; rr++) { acc[rr][0] = 0ull; acc[rr][1] = 0ull; }
#pragma unroll
                for (int i = 0; i < 16; i++) {
                    const int d4  = d4base + i;
                    const int col = d4 ^ lane;
                    ulonglong2 k0 = kb[t0 * 32 + col];
                    ulonglong2 k1 = kb[(t0 + 1) * 32 + col];
#pragma unroll
                    for (int rr = 0; rr < 4; rr++) {
                        ulonglong2 q = qb[(R + rr) * 32 + d4];
                        fma2(acc[rr][0], q.x, k0.x);
                        fma2(acc[rr][0], q.y, k0.y);
                        fma2(acc[rr][1], q.x, k1.x);
                        fma2(acc[rr][1], q.y, k1.y);
                    }
                }
                float* sr0 = sraw + (wid >> 2) * 1088;
#pragma unroll
                for (int rr = 0; rr < 4; rr++) {
                    float2 fa = unpack2(acc[rr][0]);
                    float2 fb = unpack2(acc[rr][1]);
                    sr0[t0 * 17 + R + rr]       = fa.x + fa.y;
                    sr0[(t0 + 1) * 17 + R + rr] = fb.x + fb.y;
                }
            }
            __syncthreads();

            // ---- online softmax: 256 threads, 16 per row ----
            {
                float s[4];
                bool  ok[4];
#pragma unroll
                for (int i = 0; i < 4; i++) {
                    int t = tb + i;
                    s[i]  = sraw[t * 17 + sr] + sraw[1088 + t * 17 + sr];
                    ok[i] = (jb + t) <= lim;
                    if (!ok[i]) s[i] = -1e30f;
                }
                float mx = fmaxf(fmaxf(s[0], s[1]), fmaxf(s[2], s[3]));
#pragma unroll
                for (int off = 8; off >= 1; off >>= 1)
                    mx = fmaxf(mx, __shfl_xor_sync(0xffffffffu, mx, off, 16));
                float mOld = sM[sr];
                float nm   = fmaxf(mOld, mx);
                float sum  = 0.f;
#pragma unroll
                for (int i = 0; i < 4; i++) {
                    float p = ok[i] ? __expf(s[i] - nm) : 0.f;
                    sPd[(tb + i) * 17 + sr] = make_float2(p, p);
                    sum += p;
                }
#pragma unroll
                for (int off = 8; off >= 1; off >>= 1)
                    sum += __shfl_xor_sync(0xffffffffu, sum, off, 16);
                if (sub == 0) {
                    float corr = __expf(mOld - nm);
                    sL[sr] = sL[sr] * corr + sum;
                    sM[sr] = nm;
                    sC[sr] = corr;
                }
            }
            __syncthreads();

            // ---- O += P V (packed dim-pairs) ----
            {
                u64 cc = pack2(sC[pr]);
#pragma unroll
                for (int i = 0; i < 4; i++) mul2(o[i], cc);
                const ulonglong2* vb = (const ulonglong2*)(vs4 + bufo);
                const u64* pp = (const u64*)sPd;
                const int vidx = pd >> 2;
#pragma unroll 4
                for (int t = 0; t < TT; t++) {
                    u64 p2 = pp[t * 17 + pr];
                    ulonglong2 v0 = vb[t * 32 + vidx];
                    ulonglong2 v1 = vb[t * 32 + vidx + 1];
                    fma2(o[0], p2, v0.x);
                    fma2(o[1], p2, v0.y);
                    fma2(o[2], p2, v1.x);
                    fma2(o[3], p2, v1.y);
                }
            }
            __syncthreads();

            if (it + 2 < ntiles) issue_tile(it + 2);
        }
    }

    // ---- store split partials ----
    {
        float2 f0 = unpack2(o[0]);
        float2 f1 = unpack2(o[1]);
        float2 f2 = unpack2(o[2]);
        float2 f3 = unpack2(o[3]);
        float* po = g_po + ((size_t)part * RR) * DVV;
        *(float4*)(po + pr * DVV + pd)     = make_float4(f0.x, f0.y, f1.x, f1.y);
        *(float4*)(po + pr * DVV + pd + 4) = make_float4(f2.x, f2.y, f3.x, f3.y);
        if (tid < RR) {
            g_pm[part * RR + tid] = sM[tid];
            g_pl[part * RR + tid] = sL[tid];
        }
    }
}

extern "C" __global__ void __launch_bounds__(512)
attn_reduce_kernel(float* __restrict__ out)
{
    const int hkv = blockIdx.x;
    const int b   = blockIdx.y;
    const int tid = threadIdx.x;
    const int r   = tid >> 5;          // 0..15
    const int ds  = (tid & 31) * 4;    // 0..124
    const int pb  = (b * HKV + hkv) * NSPLIT;

    float M = -1e30f;
#pragma unroll
    for (int s = 0; s < NSPLIT; s++) M = fmaxf(M, g_pm[(pb + s) * RR + r]);

    float lt = 0.f;
    float o0 = 0.f, o1 = 0.f, o2 = 0.f, o3 = 0.f;

#pragma unroll
    for (int s = 0; s < NSPLIT; s++) {
        float mm = g_pm[(pb + s) * RR + r];
        float w  = __expf(mm - M);
        lt += w * g_pl[(pb + s) * RR + r];
        float4 x = *(const float4*)(g_po + ((size_t)(pb + s) * RR + r) * DVV + ds);
        o0 += w * x.x; o1 += w * x.y; o2 += w * x.z; o3 += w * x.w;
    }

    const float inv = 1.f / lt;
    const int m  = r & 3;
    const int gi = r >> 2;
    float* dst = out + ((size_t)((b * SQ + m) * HH + hkv * GG + gi)) * DVV + ds;
    *(float4*)dst = make_float4(o0 * inv, o1 * inv, o2 * inv, o3 * inv);
}

extern "C" void kernel_launch(void* const* d_in, const int* in_sizes, int n_in,
                              void* d_out, int out_size)
{
    const float* Q  = (const float*)d_in[0];
    const float* K  = (const float*)d_in[1];
    const float* V  = (const float*)d_in[2];
    const int*   sl = (const int*)d_in[3];

    cudaFuncSetAttribute(attn_split_kernel,
                         cudaFuncAttributeMaxDynamicSharedMemorySize, SMEM_BYTES);

    attn_split_kernel<<<dim3(NSPLIT, HKV, BB), NTHREADS, SMEM_BYTES>>>(Q, K, V, sl);
    attn_reduce_kernel<<<dim3(HKV, BB), 512>>>((float*)d_out);
}

// round 4
// speedup vs baseline: 1.3098x; 1.0003x over previous
#include <cuda_runtime.h>
#include <cstdint>

#define BB 4
#define SQ 4
#define HH 32
#define HKV 8
#define GG 4
#define DD 128
#define DVV 128
#define SMAX 8192
#define RR 16
#define TT 64
#define NSPLIT 16
#define CHUNK (SMAX / NSPLIT)
#define NTHREADS 256
#define SCALE 0.08838834764831845f

// smem layout (bytes)
#define SMEM_Q_OFF 0
#define SMEM_K_OFF 8192
#define SMEM_V_OFF (8192 + 65536)
#define SMEM_SRAW_OFF (8192 + 65536 + 65536)            // [2][64][17] float = 8704
#define SMEM_PD_OFF (SMEM_SRAW_OFF + 8704)              // [64][17] float2  = 8704
#define SMEM_M_OFF (SMEM_PD_OFF + 8704)                 // sM/sL/sC 3*16 float
#define SMEM_BYTES (SMEM_M_OFF + 192)

typedef unsigned long long u64;

__device__ __forceinline__ void fma2(u64& d, u64 a, u64 b) {
    asm("fma.rn.f32x2 %0, %1, %2, %0;" : "+l"(d) : "l"(a), "l"(b));
}
__device__ __forceinline__ void mul2(u64& d, u64 a) {
    asm("mul.rn.f32x2 %0, %0, %1;" : "+l"(d) : "l"(a));
}
__device__ __forceinline__ u64 pack2(float x) {
    u64 r; asm("mov.b64 %0, {%1, %1};" : "=l"(r) : "f"(x)); return r;
}
__device__ __forceinline__ float2 unpack2(u64 a) {
    float2 f; asm("mov.b64 {%0, %1}, %2;" : "=f"(f.x), "=f"(f.y) : "l"(a)); return f;
}

// split-K partial scratch (static device memory; no allocation)
__device__ float g_po[(size_t)BB * HKV * NSPLIT * RR * DVV];
__device__ float g_pm[BB * HKV * NSPLIT * RR];
__device__ float g_pl[BB * HKV * NSPLIT * RR];

extern "C" __global__ void __launch_bounds__(NTHREADS, 1)
attn_split_kernel(const float* __restrict__ Q, const float* __restrict__ K,
                  const float* __restrict__ V, const int* __restrict__ seqlens)
{
    extern __shared__ char smem[];
    float4* qs4  = (float4*)(smem + SMEM_Q_OFF);
    float4* ks4  = (float4*)(smem + SMEM_K_OFF);
    float4* vs4  = (float4*)(smem + SMEM_V_OFF);
    float*  sraw = (float*)(smem + SMEM_SRAW_OFF);     // [dh][t][17]
    float2* sPd  = (float2*)(smem + SMEM_PD_OFF);      // [t][17]
    float*  sM   = (float*)(smem + SMEM_M_OFF);
    float*  sL   = sM + 16;
    float*  sC   = sM + 32;

    const int split = blockIdx.x;
    const int hkv   = blockIdx.y;
    const int b     = blockIdx.z;
    const int tid   = threadIdx.x;
    const int lane  = tid & 31;
    const int wid   = tid >> 5;

    const int L  = seqlens[b];
    const int c0 = split * CHUNK;
    int n_eff = L - c0;
    if (n_eff > CHUNK) n_eff = CHUNK;
    const int part = (b * HKV + hkv) * NSPLIT + split;

    if (tid < RR) { sM[tid] = -1e30f; sL[tid] = 0.f; }

    // PV ownership: warp owns d-cols [16*wid,16*wid+16)
    const int pr = lane >> 1;                       // row 0..15
    const int pd = (wid << 4) + ((lane & 1) << 3);  // d base (8 floats)
    u64 o[4];
#pragma unroll
    for (int i = 0; i < 4; i++) o[i] = 0ull;

    if (n_eff > 0) {
        // ---- Q (pre-scaled) into smem ----
#pragma unroll
        for (int i = 0; i < 2; i++) {
            int f  = tid * 2 + i;
            int r  = f >> 5;
            int d4 = f & 31;
            int h  = hkv * GG + (r >> 2);
            int m  = r & 3;
            const float4 qv = *(const float4*)(Q + ((size_t)((b * SQ + m) * HH + h)) * DD + d4 * 4);
            float4 qq;
            qq.x = qv.x * SCALE; qq.y = qv.y * SCALE;
            qq.z = qv.z * SCALE; qq.w = qv.w * SCALE;
            qs4[f] = qq;
        }
        __syncthreads();

        const int ntiles = (n_eff + TT - 1) / TT;
        const size_t kvbase = ((size_t)b * SMAX * HKV + hkv) * DD;

        auto issue_tile = [&](int it) {
            const int jb   = c0 + it * TT;
            const int bufo = (it & 1) * (TT * 32);
#pragma unroll
            for (int i = 0; i < 8; i++) {
                int f  = i * NTHREADS + tid;
                int t  = f >> 5;
                int d4 = f & 31;
                const float* gk = K + kvbase + (size_t)(jb + t) * (HKV * DD) + d4 * 4;
                const float* gv = V + kvbase + (size_t)(jb + t) * (HKV * DD) + d4 * 4;
                unsigned ka = (unsigned)__cvta_generic_to_shared(&ks4[bufo + t * 32 + (d4 ^ ((t >> 1) & 31))]);
                unsigned va = (unsigned)__cvta_generic_to_shared(&vs4[bufo + t * 32 + d4]);
                asm volatile("cp.async.cg.shared.global [%0], [%1], 16;\n" :: "r"(ka), "l"(gk));
                asm volatile("cp.async.cg.shared.global [%0], [%1], 16;\n" :: "r"(va), "l"(gv));
            }
            asm volatile("cp.async.commit_group;\n" ::: "memory");
        };

        issue_tile(0);
        if (ntiles > 1) issue_tile(1);

        // QK mapping: warp wid -> rows 4*(wid&3)..+3, dim-half (wid>>2)
        const int R      = (wid & 3) * 4;
        const int d4base = (wid >> 2) * 16;
        const int t0     = 2 * lane;
        // softmax mapping
        const int sr  = tid >> 4;
        const int sub = tid & 15;
        const int tb  = sub * 4;
        const int lim = L - SQ + (sr & 3);

        for (int it = 0; it < ntiles; ++it) {
            if (it < ntiles - 1) asm volatile("cp.async.wait_group 1;\n" ::: "memory");
            else                 asm volatile("cp.async.wait_group 0;\n" ::: "memory");
            __syncthreads();

            const int jb   = c0 + it * TT;
            const int bufo = (it & 1) * (TT * 32);

            // ---- S = Q K^T : 4 rows x 2 tokens per thread, packed dim-pairs ----
            {
                const ulonglong2* kb = (const ulonglong2*)(ks4 + bufo);
                const ulonglong2* qb = (const ulonglong2*)qs4;
                u64 acc[4][2];
#pragma unroll
                for (int rr = 0; rr < 4; rr++) { acc[rr][0] = 0ull; acc[rr][1] = 0ull; }
#pragma unroll
                for (int i = 0; i < 16; i++) {
                    const int d4  = d4base + i;
                    const int col = d4 ^ lane;
                    ulonglong2 k0 = kb[t0 * 32 + col];
                    ulonglong2 k1 = kb[(t0 + 1) * 32 + col];
#pragma unroll
                    for (int rr = 0; rr < 4; rr++) {
                        ulonglong2 q = qb[(R + rr) * 32 + d4];
                        fma2(acc[rr][0], q.x, k0.x);
                        fma2(acc[rr][0], q.y, k0.y);
                        fma2(acc[rr][1], q.x, k1.x);
                        fma2(acc[rr][1], q.y, k1.y);
                    }
                }
                float* sr0 = sraw + (wid >> 2) * 1088;
#pragma unroll
                for (int rr = 0; rr < 4; rr++) {
                    float2 fa = unpack2(acc[rr][0]);
                    float2 fb = unpack2(acc[rr][1]);
                    sr0[t0 * 17 + R + rr]       = fa.x + fa.y;
                    sr0[(t0 + 1) * 17 + R + rr] = fb.x + fb.y;
                }
            }
            __syncthreads();

            // ---- online softmax: 256 threads, 16 per row ----
            {
                float s[4];
                bool  ok[4];
#pragma unroll
                for (int i = 0; i < 4; i++) {
                    int t = tb + i;
                    s[i]  = sraw[t * 17 + sr] + sraw[1088 + t * 17 + sr];
                    ok[i] = (jb + t) <= lim;
                    if (!ok[i]) s[i] = -1e30f;
                }
                float mx = fmaxf(fmaxf(s[0], s[1]), fmaxf(s[2], s[3]));
#pragma unroll
                for (int off = 8; off >= 1; off >>= 1)
                    mx = fmaxf(mx, __shfl_xor_sync(0xffffffffu, mx, off, 16));
                float mOld = sM[sr];
                float nm   = fmaxf(mOld, mx);
                float sum  = 0.f;
#pragma unroll
                for (int i = 0; i < 4; i++) {
                    float p = ok[i] ? __expf(s[i] - nm) : 0.f;
                    sPd[(tb + i) * 17 + sr] = make_float2(p, p);
                    sum += p;
                }
#pragma unroll
                for (int off = 8; off >= 1; off >>= 1)
                    sum += __shfl_xor_sync(0xffffffffu, sum, off, 16);
                if (sub == 0) {
                    float corr = __expf(mOld - nm);
                    sL[sr] = sL[sr] * corr + sum;
                    sM[sr] = nm;
                    sC[sr] = corr;
                }
            }
            __syncthreads();

            // ---- O += P V (packed dim-pairs) ----
            {
                u64 cc = pack2(sC[pr]);
#pragma unroll
                for (int i = 0; i < 4; i++) mul2(o[i], cc);
                const ulonglong2* vb = (const ulonglong2*)(vs4 + bufo);
                const u64* pp = (const u64*)sPd;
                const int vidx = pd >> 2;
#pragma unroll 4
                for (int t = 0; t < TT; t++) {
                    u64 p2 = pp[t * 17 + pr];
                    ulonglong2 v0 = vb[t * 32 + vidx];
                    ulonglong2 v1 = vb[t * 32 + vidx + 1];
                    fma2(o[0], p2, v0.x);
                    fma2(o[1], p2, v0.y);
                    fma2(o[2], p2, v1.x);
                    fma2(o[3], p2, v1.y);
                }
            }
            __syncthreads();

            if (it + 2 < ntiles) issue_tile(it + 2);
        }
    }

    // ---- store split partials ----
    {
        float2 f0 = unpack2(o[0]);
        float2 f1 = unpack2(o[1]);
        float2 f2 = unpack2(o[2]);
        float2 f3 = unpack2(o[3]);
        float* po = g_po + ((size_t)part * RR) * DVV;
        *(float4*)(po + pr * DVV + pd)     = make_float4(f0.x, f0.y, f1.x, f1.y);
        *(float4*)(po + pr * DVV + pd + 4) = make_float4(f2.x, f2.y, f3.x, f3.y);
        if (tid < RR) {
            g_pm[part * RR + tid] = sM[tid];
            g_pl[part * RR + tid] = sL[tid];
        }
    }
}

extern "C" __global__ void __launch_bounds__(512)
attn_reduce_kernel(float* __restrict__ out)
{
    const int hkv = blockIdx.x;
    const int b   = blockIdx.y;
    const int tid = threadIdx.x;
    const int r   = tid >> 5;          // 0..15
    const int ds  = (tid & 31) * 4;    // 0..124
    const int pb  = (b * HKV + hkv) * NSPLIT;

    float M = -1e30f;
#pragma unroll
    for (int s = 0; s < NSPLIT; s++) M = fmaxf(M, g_pm[(pb + s) * RR + r]);

    float lt = 0.f;
    float o0 = 0.f, o1 = 0.f, o2 = 0.f, o3 = 0.f;

#pragma unroll
    for (int s = 0; s < NSPLIT; s++) {
        float mm = g_pm[(pb + s) * RR + r];
        float w  = __expf(mm - M);
        lt += w * g_pl[(pb + s) * RR + r];
        float4 x = *(const float4*)(g_po + ((size_t)(pb + s) * RR + r) * DVV + ds);
        o0 += w * x.x; o1 += w * x.y; o2 += w * x.z; o3 += w * x.w;
    }

    const float inv = 1.f / lt;
    const int m  = r & 3;
    const int gi = r >> 2;
    float* dst = out + ((size_t)((b * SQ + m) * HH + hkv * GG + gi)) * DVV + ds;
    *(float4*)dst = make_float4(o0 * inv, o1 * inv, o2 * inv, o3 * inv);
}

extern "C" void kernel_launch(void* const* d_in, const int* in_sizes, int n_in,
                              void* d_out, int out_size)
{
    const float* Q  = (const float*)d_in[0];
    const float* K  = (const float*)d_in[1];
    const float* V  = (const float*)d_in[2];
    const int*   sl = (const int*)d_in[3];

    cudaFuncSetAttribute(attn_split_kernel,
                         cudaFuncAttributeMaxDynamicSharedMemorySize, SMEM_BYTES);

    attn_split_kernel<<<dim3(NSPLIT, HKV, BB), NTHREADS, SMEM_BYTES>>>(Q, K, V, sl);
    attn_reduce_kernel<<<dim3(HKV, BB), 512>>>((float*)d_out);
}

// round 5
// speedup vs baseline: 1.5102x; 1.1529x over previous
#include <cuda_runtime.h>
#include <cstdint>

#define BB 4
#define SQ 4
#define HH 32
#define HKV 8
#define GG 4
#define DD 128
#define DVV 128
#define SMAX 8192
#define RR 16
#define TT 32
#define NSPLIT 32
#define CHUNK (SMAX / NSPLIT)
#define NTHREADS 128
#define SCALE 0.08838834764831845f

// smem layout (bytes)
#define SMEM_Q_OFF 0
#define SMEM_K_OFF 8192
#define SMEM_V_OFF (8192 + 32768)
#define SMEM_SRAW_OFF (8192 + 32768 + 32768)          // [2][32][17] float = 4352
#define SMEM_PD_OFF (SMEM_SRAW_OFF + 4352)            // [16][34] float2  = 4352
#define SMEM_M_OFF (SMEM_PD_OFF + 4352)               // sM/sL/sC 3*16 float
#define SMEM_BYTES (SMEM_M_OFF + 192)

typedef unsigned long long u64;

__device__ __forceinline__ void fma2(u64& d, u64 a, u64 b) {
    asm("fma.rn.f32x2 %0, %1, %2, %0;" : "+l"(d) : "l"(a), "l"(b));
}
__device__ __forceinline__ void mul2(u64& d, u64 a) {
    asm("mul.rn.f32x2 %0, %0, %1;" : "+l"(d) : "l"(a));
}
__device__ __forceinline__ u64 pack2(float x) {
    u64 r; asm("mov.b64 %0, {%1, %1};" : "=l"(r) : "f"(x)); return r;
}
__device__ __forceinline__ float2 unpack2(u64 a) {
    float2 f; asm("mov.b64 {%0, %1}, %2;" : "=f"(f.x), "=f"(f.y) : "l"(a)); return f;
}

// split-K partial scratch (static device memory; no allocation)
__device__ float g_po[(size_t)BB * HKV * NSPLIT * RR * DVV];
__device__ float g_pm[BB * HKV * NSPLIT * RR];
__device__ float g_pl[BB * HKV * NSPLIT * RR];

extern "C" __global__ void __launch_bounds__(NTHREADS, 2)
attn_split_kernel(const float* __restrict__ Q, const float* __restrict__ K,
                  const float* __restrict__ V, const int* __restrict__ seqlens)
{
    extern __shared__ char smem[];
    float4* qs4  = (float4*)(smem + SMEM_Q_OFF);
    float4* ks4  = (float4*)(smem + SMEM_K_OFF);
    float4* vs4  = (float4*)(smem + SMEM_V_OFF);
    float*  sraw = (float*)(smem + SMEM_SRAW_OFF);   // [dh][t][17]
    float2* sPd  = (float2*)(smem + SMEM_PD_OFF);    // [r][34]
    float*  sM   = (float*)(smem + SMEM_M_OFF);
    float*  sL   = sM + 16;
    float*  sC   = sM + 32;

    const int split = blockIdx.x;
    const int hkv   = blockIdx.y;
    const int b     = blockIdx.z;
    const int tid   = threadIdx.x;
    const int lane  = tid & 31;
    const int wid   = tid >> 5;

    const int L  = seqlens[b];
    const int c0 = split * CHUNK;
    int n_eff = L - c0;
    if (n_eff > CHUNK) n_eff = CHUNK;
    const int part = (b * HKV + hkv) * NSPLIT + split;

    if (tid < RR) { sM[tid] = -1e30f; sL[tid] = 0.f; }

    // PV ownership: warp owns d-cols [32*wid, 32*wid+32)
    const int pr   = lane >> 1;                        // row 0..15
    const int pd   = (wid << 5) + ((lane & 1) << 4);   // d base (16 floats)
    const int vidx = pd >> 2;                          // float4 column
    u64 o[8];
#pragma unroll
    for (int i = 0; i < 8; i++) o[i] = 0ull;

    if (n_eff > 0) {
        // ---- Q (pre-scaled) into smem ----
#pragma unroll
        for (int i = 0; i < 4; i++) {
            int f  = i * NTHREADS + tid;
            int r  = f >> 5;
            int d4 = f & 31;
            int h  = hkv * GG + (r >> 2);
            int m  = r & 3;
            const float4 qv = *(const float4*)(Q + ((size_t)((b * SQ + m) * HH + h)) * DD + d4 * 4);
            float4 qq;
            qq.x = qv.x * SCALE; qq.y = qv.y * SCALE;
            qq.z = qv.z * SCALE; qq.w = qv.w * SCALE;
            qs4[f] = qq;
        }
        __syncthreads();

        const int ntiles = (n_eff + TT - 1) / TT;
        const size_t kvbase = ((size_t)b * SMAX * HKV + hkv) * DD;

        auto issue_tile = [&](int it) {
            const int jb   = c0 + it * TT;
            const int bufo = (it & 1) * (TT * 32);
#pragma unroll
            for (int i = 0; i < 8; i++) {
                int f  = i * NTHREADS + tid;   // 0..1023
                int t  = f >> 5;
                int d4 = f & 31;
                const float* gk = K + kvbase + (size_t)(jb + t) * (HKV * DD) + d4 * 4;
                const float* gv = V + kvbase + (size_t)(jb + t) * (HKV * DD) + d4 * 4;
                unsigned ka = (unsigned)__cvta_generic_to_shared(&ks4[bufo + t * 32 + (d4 ^ t)]);
                unsigned va = (unsigned)__cvta_generic_to_shared(&vs4[bufo + t * 32 + d4]);
                asm volatile("cp.async.cg.shared.global [%0], [%1], 16;\n" :: "r"(ka), "l"(gk));
                asm volatile("cp.async.cg.shared.global [%0], [%1], 16;\n" :: "r"(va), "l"(gv));
            }
            asm volatile("cp.async.commit_group;\n" ::: "memory");
        };

        issue_tile(0);
        if (ntiles > 1) issue_tile(1);

        // QK mapping: warp -> rows (wid>>1)*8..+7, dim-half (wid&1); lane = token
        const int dh = wid & 1;
        const int R  = (wid >> 1) * 8;
        // softmax mapping: 8 threads per row, 4 tokens each
        const int sr  = tid >> 3;
        const int sub = tid & 7;
        const int tb  = sub * 4;
        const int lim = L - SQ + (sr & 3);

        for (int it = 0; it < ntiles; ++it) {
            if (it < ntiles - 1) asm volatile("cp.async.wait_group 1;\n" ::: "memory");
            else                 asm volatile("cp.async.wait_group 0;\n" ::: "memory");
            __syncthreads();

            const int jb   = c0 + it * TT;
            const int bufo = (it & 1) * (TT * 32);

            // ---- S = Q K^T : 8 rows x 1 token per thread, packed dim-pairs ----
            {
                const ulonglong2* kb = (const ulonglong2*)(ks4 + bufo);
                const ulonglong2* qb = (const ulonglong2*)qs4;
                u64 acc[8];
#pragma unroll
                for (int rr = 0; rr < 8; rr++) acc[rr] = 0ull;
#pragma unroll
                for (int i = 0; i < 16; i++) {
                    const int d4 = dh * 16 + i;
                    ulonglong2 k = kb[lane * 32 + (d4 ^ lane)];
#pragma unroll
                    for (int rr = 0; rr < 8; rr++) {
                        ulonglong2 q = qb[(R + rr) * 32 + d4];
                        fma2(acc[rr], q.x, k.x);
                        fma2(acc[rr], q.y, k.y);
                    }
                }
                float* sr0 = sraw + dh * 544;
#pragma unroll
                for (int rr = 0; rr < 8; rr++) {
                    float2 f = unpack2(acc[rr]);
                    sr0[lane * 17 + R + rr] = f.x + f.y;
                }
            }
            __syncthreads();

            // ---- online softmax: 128 threads, 8 per row ----
            {
                float s[4];
                bool  ok[4];
#pragma unroll
                for (int i = 0; i < 4; i++) {
                    int t = tb + i;
                    s[i]  = sraw[t * 17 + sr] + sraw[544 + t * 17 + sr];
                    ok[i] = (jb + t) <= lim;
                    if (!ok[i]) s[i] = -1e30f;
                }
                float mx = fmaxf(fmaxf(s[0], s[1]), fmaxf(s[2], s[3]));
#pragma unroll
                for (int off = 4; off >= 1; off >>= 1)
                    mx = fmaxf(mx, __shfl_xor_sync(0xffffffffu, mx, off, 8));
                float mOld = sM[sr];
                float nm   = fmaxf(mOld, mx);
                float sum  = 0.f;
#pragma unroll
                for (int i = 0; i < 4; i++) {
                    float p = ok[i] ? __expf(s[i] - nm) : 0.f;
                    sPd[sr * 34 + tb + i] = make_float2(p, p);
                    sum += p;
                }
#pragma unroll
                for (int off = 4; off >= 1; off >>= 1)
                    sum += __shfl_xor_sync(0xffffffffu, sum, off, 8);
                if (sub == 0) {
                    float corr = __expf(mOld - nm);
                    sL[sr] = sL[sr] * corr + sum;
                    sM[sr] = nm;
                    sC[sr] = corr;
                }
            }
            __syncthreads();

            // ---- O += P V (packed dim-pairs, 2 tokens per p-load) ----
            {
                u64 cc = pack2(sC[pr]);
#pragma unroll
                for (int i = 0; i < 8; i++) mul2(o[i], cc);
                const ulonglong2* vb = (const ulonglong2*)(vs4 + bufo);
                const ulonglong2* pp = (const ulonglong2*)sPd;   // 2 float2 per elem
#pragma unroll 4
                for (int tp = 0; tp < 16; tp++) {
                    ulonglong2 p2 = pp[pr * 17 + tp];  // {p_t0,p_t0},{p_t1,p_t1}
                    const int t0 = 2 * tp;
                    ulonglong2 v0 = vb[t0 * 32 + vidx];
                    ulonglong2 v1 = vb[t0 * 32 + vidx + 1];
                    ulonglong2 v2 = vb[t0 * 32 + vidx + 2];
                    ulonglong2 v3 = vb[t0 * 32 + vidx + 3];
                    fma2(o[0], p2.x, v0.x); fma2(o[1], p2.x, v0.y);
                    fma2(o[2], p2.x, v1.x); fma2(o[3], p2.x, v1.y);
                    fma2(o[4], p2.x, v2.x); fma2(o[5], p2.x, v2.y);
                    fma2(o[6], p2.x, v3.x); fma2(o[7], p2.x, v3.y);
                    ulonglong2 w0 = vb[(t0 + 1) * 32 + vidx];
                    ulonglong2 w1 = vb[(t0 + 1) * 32 + vidx + 1];
                    ulonglong2 w2 = vb[(t0 + 1) * 32 + vidx + 2];
                    ulonglong2 w3 = vb[(t0 + 1) * 32 + vidx + 3];
                    fma2(o[0], p2.y, w0.x); fma2(o[1], p2.y, w0.y);
                    fma2(o[2], p2.y, w1.x); fma2(o[3], p2.y, w1.y);
                    fma2(o[4], p2.y, w2.x); fma2(o[5], p2.y, w2.y);
                    fma2(o[6], p2.y, w3.x); fma2(o[7], p2.y, w3.y);
                }
            }
            __syncthreads();

            if (it + 2 < ntiles) issue_tile(it + 2);
        }
    }

    // ---- store split partials ----
    {
        float* po = g_po + ((size_t)part * RR) * DVV + pr * DVV + pd;
#pragma unroll
        for (int i = 0; i < 4; i++) {
            float2 a = unpack2(o[2 * i]);
            float2 bf = unpack2(o[2 * i + 1]);
            *(float4*)(po + 4 * i) = make_float4(a.x, a.y, bf.x, bf.y);
        }
        if (tid < RR) {
            g_pm[part * RR + tid] = sM[tid];
            g_pl[part * RR + tid] = sL[tid];
        }
    }
}

extern "C" __global__ void __launch_bounds__(128)
attn_reduce_kernel(float* __restrict__ out)
{
    const int hkv = blockIdx.x;
    const int b   = blockIdx.y;
    const int r   = blockIdx.z;        // 0..15
    const int d   = threadIdx.x;       // 0..127
    const int pb  = (b * HKV + hkv) * NSPLIT;

    float M = -1e30f;
#pragma unroll
    for (int s = 0; s < NSPLIT; s++) M = fmaxf(M, g_pm[(pb + s) * RR + r]);

    float lt = 0.f;
    float acc = 0.f;
#pragma unroll
    for (int s = 0; s < NSPLIT; s++) {
        float mm = g_pm[(pb + s) * RR + r];
        float w  = __expf(mm - M);
        lt  += w * g_pl[(pb + s) * RR + r];
        acc += w * g_po[((size_t)(pb + s) * RR + r) * DVV + d];
    }

    const int m  = r & 3;
    const int gi = r >> 2;
    out[((size_t)((b * SQ + m) * HH + hkv * GG + gi)) * DVV + d] = acc / lt;
}

extern "C" void kernel_launch(void* const* d_in, const int* in_sizes, int n_in,
                              void* d_out, int out_size)
{
    const float* Q  = (const float*)d_in[0];
    const float* K  = (const float*)d_in[1];
    const float* V  = (const float*)d_in[2];
    const int*   sl = (const int*)d_in[3];

    cudaFuncSetAttribute(attn_split_kernel,
                         cudaFuncAttributeMaxDynamicSharedMemorySize, SMEM_BYTES);

    attn_split_kernel<<<dim3(NSPLIT, HKV, BB), NTHREADS, SMEM_BYTES>>>(Q, K, V, sl);
    attn_reduce_kernel<<<dim3(HKV, BB, RR), 128>>>((float*)d_out);
}